// round 11
// baseline (speedup 1.0000x reference)
#include <cuda_runtime.h>
#include <cuda_bf16.h>
#include <math.h>
#include <stdint.h>

#define BD 8
#define SL 2048
#define DM 256
#define HN 4
#define DH 64
#define MR (BD*SL)   // 16384

// Scratch (device globals; allocation-free per harness rules)
__device__ float g_qkv[MR*768];
__device__ __nv_bfloat16 g_Qh[BD*HN*SL*DH];   // roped, pre-scaled by 0.125*log2(e)
__device__ __nv_bfloat16 g_Kh[BD*HN*SL*DH];   // roped
__device__ __nv_bfloat16 g_Vr[BD*HN*SL*DH];   // row-major [s][d]
__device__ __nv_bfloat16 g_Vt[BD*HN*DH*SL];   // transposed [d][s]
__device__ float g_ctx[MR*DM];
__device__ float g_msg[MR*DM];
__device__ float g_ff[MR*2*DM];

// ---- helpers ----------------------------------------------------------------
__device__ __forceinline__ void mma8(float* c, const uint32_t* a, uint32_t b0, uint32_t b1) {
    asm volatile(
        "mma.sync.aligned.m16n8k8.row.col.f32.tf32.tf32.f32 "
        "{%0,%1,%2,%3},{%4,%5,%6,%7},{%8,%9},{%0,%1,%2,%3};"
        : "+f"(c[0]), "+f"(c[1]), "+f"(c[2]), "+f"(c[3])
        : "r"(a[0]), "r"(a[1]), "r"(a[2]), "r"(a[3]), "r"(b0), "r"(b1));
}
__device__ __forceinline__ void mma16(float* c, const uint32_t* a, uint32_t b0, uint32_t b1) {
    asm volatile(
        "mma.sync.aligned.m16n8k16.row.col.f32.bf16.bf16.f32 "
        "{%0,%1,%2,%3},{%4,%5,%6,%7},{%8,%9},{%0,%1,%2,%3};"
        : "+f"(c[0]), "+f"(c[1]), "+f"(c[2]), "+f"(c[3])
        : "r"(a[0]), "r"(a[1]), "r"(a[2]), "r"(a[3]), "r"(b0), "r"(b1));
}
__device__ __forceinline__ void ldsm4(uint32_t& r0, uint32_t& r1, uint32_t& r2, uint32_t& r3,
                                      uint32_t addr) {
    asm volatile("ldmatrix.sync.aligned.m8n8.x4.shared.b16 {%0,%1,%2,%3}, [%4];"
        : "=r"(r0), "=r"(r1), "=r"(r2), "=r"(r3) : "r"(addr));
}
__device__ __forceinline__ void stsm4(uint32_t addr, uint32_t r0, uint32_t r1,
                                      uint32_t r2, uint32_t r3) {
    asm volatile("stmatrix.sync.aligned.m8n8.x4.shared.b16 [%0], {%1,%2,%3,%4};"
        :: "r"(addr), "r"(r0), "r"(r1), "r"(r2), "r"(r3));
}
__device__ __forceinline__ void cp16(uint32_t saddr, const void* gaddr) {
    asm volatile("cp.async.cg.shared.global [%0], [%1], 16;" :: "r"(saddr), "l"(gaddr));
}
__device__ __forceinline__ void cp_commit() { asm volatile("cp.async.commit_group;"); }
template<int N> __device__ __forceinline__ void cp_wait() {
    asm volatile("cp.async.wait_group %0;" :: "n"(N));
}
__device__ __forceinline__ uint32_t packbf(float a, float b) {
    __nv_bfloat162 h = __floats2bfloat162_rn(a, b);
    return *(uint32_t*)&h;
}

// ---------------------------------------------------------------------------
// Tensor-core GEMM (TF32, cp.async 3-stage, dynamic smem): C = A @ W^T + bias.
// BM=128, BN=128, BK=16. 8 warps (4M x 2N), warp tile 32x64.
// ---------------------------------------------------------------------------
#define AST 20
#define GEMM_SMEM (3*2*128*AST*4)   // 61440 bytes
template<int MODE, bool CONCAT>
__global__ __launch_bounds__(256) void gemm_tc(
    const float* __restrict__ A, const float* __restrict__ A2,
    const float* __restrict__ W, const float* __restrict__ bias,
    float* __restrict__ C, const float* __restrict__ res,
    int M, int N, int K)
{
    extern __shared__ float dsm[];
    float* Asm = dsm;                  // [3][128*AST]
    float* Bsm = dsm + 3*128*AST;      // [3][128*AST]
    const int t = threadIdx.x;
    const int w = t >> 5, wm = w & 3, wn = w >> 2;
    const int lane = t & 31, lr4 = lane >> 2, lc4 = lane & 3;
    const int m0 = blockIdx.y << 7, n0 = blockIdx.x << 7;

    float acc[2][8][4] = {};

    const int ldr = t >> 1;
    const int ldc = (t & 1) << 3;

    uint32_t sA = (uint32_t)__cvta_generic_to_shared(Asm);
    uint32_t sB = (uint32_t)__cvta_generic_to_shared(Bsm);
    const uint32_t stg = 128*AST*4;

    auto issue_stage = [&](int k0, int buf) {
        int kk = k0 + ldc;
        const float* asrc;
        if (CONCAT) asrc = (kk >= 256) ? (A2 + (size_t)(m0 + ldr) * 256 + kk - 256)
                                       : (A  + (size_t)(m0 + ldr) * 256 + kk);
        else        asrc = A + (size_t)(m0 + ldr) * K + kk;
        uint32_t da = sA + buf*stg + (ldr*AST + ldc)*4;
        cp16(da,      asrc);
        cp16(da + 16, asrc + 4);
        const float* bsrc = W + (size_t)(n0 + ldr) * K + k0 + ldc;
        uint32_t db = sB + buf*stg + (ldr*AST + ldc)*4;
        cp16(db,      bsrc);
        cp16(db + 16, bsrc + 4);
        cp_commit();
    };

    issue_stage(0, 0);
    issue_stage(16, 1);

    const int niters = K >> 4;
    int cur = 0;
    for (int it = 0; it < niters; it++) {
        cp_wait<1>();
        __syncthreads();
        if (it + 2 < niters) issue_stage((it + 2) << 4, (it + 2) % 3);

        const uint32_t* Ac = (const uint32_t*)(Asm + cur*128*AST);
        const uint32_t* Bc = (const uint32_t*)(Bsm + cur*128*AST);
        #pragma unroll
        for (int ks = 0; ks < 2; ks++) {
            const int kb = ks << 3;
            uint32_t a[2][4];
            #pragma unroll
            for (int mi = 0; mi < 2; mi++) {
                int r = wm*32 + mi*16 + lr4, c = kb + lc4;
                a[mi][0] = Ac[r*AST + c];     a[mi][1] = Ac[(r+8)*AST + c];
                a[mi][2] = Ac[r*AST + c + 4]; a[mi][3] = Ac[(r+8)*AST + c + 4];
            }
            #pragma unroll
            for (int ni = 0; ni < 8; ni++) {
                int r = wn*64 + ni*8 + lr4, c = kb + lc4;
                uint32_t b0 = Bc[r*AST + c], b1 = Bc[r*AST + c + 4];
                mma8(acc[0][ni], a[0], b0, b1);
                mma8(acc[1][ni], a[1], b0, b1);
            }
        }
        __syncthreads();
        cur = (cur + 1 == 3) ? 0 : cur + 1;
    }

    #pragma unroll
    for (int mi = 0; mi < 2; mi++) {
        #pragma unroll
        for (int ni = 0; ni < 8; ni++) {
            int gm = m0 + wm*32 + mi*16 + lr4;
            int gn = n0 + wn*64 + ni*8 + 2*lc4;
            float b0 = bias[gn], b1 = bias[gn+1];
            float v00 = acc[mi][ni][0] + b0, v01 = acc[mi][ni][1] + b1;
            float v10 = acc[mi][ni][2] + b0, v11 = acc[mi][ni][3] + b1;
            if (MODE == 2) {
                const float* r0 = res + (size_t)gm * N + gn;
                const float* r1 = res + (size_t)(gm+8) * N + gn;
                v00 += r0[0]; v01 += r0[1]; v10 += r1[0]; v11 += r1[1];
            }
            *(float2*)(C + (size_t)gm * N + gn)     = make_float2(v00, v01);
            *(float2*)(C + (size_t)(gm+8) * N + gn) = make_float2(v10, v11);
        }
    }
}

// ---------------------------------------------------------------------------
// Repack qkv [M,768] -> bf16 Q (roped + scaled by 0.125*log2e), K (roped), V.
// ---------------------------------------------------------------------------
__global__ __launch_bounds__(256) void repack_rope_kernel(const float* __restrict__ kp)
{
    int idx = blockIdx.x * blockDim.x + threadIdx.x;   // B*H*S*32 pairs
    int d2 = idx & 31;
    int s  = (idx >> 5) & (SL - 1);
    int h  = (idx >> 16) & (HN - 1);
    int b  = idx >> 18;

    int gm = b * SL + s;
    const float* src = g_qkv + (size_t)gm * 768 + h * 192 + 6 * d2;
    float q0 = src[0], k0 = src[1], v0 = src[2];
    float q1 = src[3], k1 = src[4], v1 = src[5];

    const int SIN_OFF = BD * SL * DH;
    int kb = (b * SL + s) * DH + (d2 << 1);
    float c0 = kp[kb],           c1 = kp[kb + 1];
    float s0 = kp[SIN_OFF + kb], s1 = kp[SIN_OFF + kb + 1];

    int base = (((b * HN + h) * SL) + s) * DH + (d2 << 1);
    const float scale = 0.125f * 1.4426950408889634f;   // Dh^-0.5 * log2(e)
    *(__nv_bfloat162*)&g_Qh[base] =
        __floats2bfloat162_rn((q0*c0 - q1*s0)*scale, (q1*c1 + q0*s1)*scale);
    *(__nv_bfloat162*)&g_Kh[base] =
        __floats2bfloat162_rn(k0*c0 - k1*s0, k1*c1 + k0*s1);
    *(__nv_bfloat162*)&g_Vr[base] = __floats2bfloat162_rn(v0, v1);
}

// ---------------------------------------------------------------------------
// V transpose: g_Vr [bh][s][d] -> g_Vt [bh][d][s], 64x64 smem tiles
// ---------------------------------------------------------------------------
__global__ __launch_bounds__(256) void vtrans_kernel()
{
    __shared__ uint32_t tile[64*33];
    const int t = threadIdx.x;
    const int bh = blockIdx.y;
    const int s0 = blockIdx.x << 6;

    {
        int sr = t >> 2, wc = (t & 3) * 8;
        const uint32_t* src = (const uint32_t*)(g_Vr + (size_t)bh*SL*DH + (size_t)(s0+sr)*DH) + wc;
        #pragma unroll
        for (int i = 0; i < 8; i++) tile[sr*33 + wc + i] = src[i];
    }
    __syncthreads();
    {
        int d = t >> 2, sc = (t & 3) * 16;
        uint32_t outw[8];
        #pragma unroll
        for (int j = 0; j < 8; j++) {
            uint32_t w0 = tile[(sc + 2*j    )*33 + (d >> 1)];
            uint32_t w1 = tile[(sc + 2*j + 1)*33 + (d >> 1)];
            uint32_t lo = (d & 1) ? (w0 >> 16) : (w0 & 0xffffu);
            uint32_t hi = (d & 1) ? (w1 >> 16) : (w1 & 0xffffu);
            outw[j] = lo | (hi << 16);
        }
        uint32_t* dst = (uint32_t*)(g_Vt + (size_t)bh*DH*SL + (size_t)d*SL + s0 + sc);
        *(uint4*)dst       = make_uint4(outw[0], outw[1], outw[2], outw[3]);
        *(uint4*)(dst + 4) = make_uint4(outw[4], outw[5], outw[6], outw[7]);
    }
}

// ---------------------------------------------------------------------------
// Flash attention, bf16 m16n8k16, ldmatrix/stmatrix, exp2 softmax.
// CTA: 128 queries x 64-key tiles. 8 warps: 4(M, 32 rows each) x 2(N).
// Dynamic smem: Ks[2] | Vts[2] | Ps(128 rows) | lsum.
// ---------------------------------------------------------------------------
#define KW 36   // smem row stride in 4B words (72 bf16)
#define ATTN_SMEM ((2*64*KW + 2*64*KW + 128*KW)*4 + 2*128*4)   // 56320 B
__global__ __launch_bounds__(256) void attn_kernel(float* __restrict__ ctx)
{
    extern __shared__ uint32_t asm_[];
    uint32_t* Ks  = asm_;                    // [2][64*KW]
    uint32_t* Vts = asm_ + 2*64*KW;          // [2][64*KW]
    uint32_t* Ps  = asm_ + 4*64*KW;          // [128*KW]
    float* lsum   = (float*)(asm_ + 4*64*KW + 128*KW);   // [2][128]

    const int t = threadIdx.x;
    const int w = t >> 5, wm = w & 3, wn = w >> 2;
    const int lane = t & 31, g = lane >> 2, tg = lane & 3;
    const int r8 = lane & 7;
    const int selA = (lane >> 3) & 1;
    const int selB = (lane >> 4) & 1;
    const int bh = blockIdx.y;
    const int m0 = blockIdx.x << 7;          // 128 queries per CTA

    const __nv_bfloat16* Qb  = g_Qh + (size_t)bh * SL * DH;
    const __nv_bfloat16* Kb  = g_Kh + (size_t)bh * SL * DH;
    const __nv_bfloat16* Vtb = g_Vt + (size_t)bh * DH * SL;

    // Q fragments: 2 m-tiles x 4 k-steps x 4 regs
    uint32_t qf[2][4][4];
    {
        const uint32_t* Qw = (const uint32_t*)Qb;   // 32 words per row
        #pragma unroll
        for (int mi = 0; mi < 2; mi++) {
            int r = m0 + wm*32 + mi*16 + g;
            #pragma unroll
            for (int kk = 0; kk < 4; kk++) {
                qf[mi][kk][0] = Qw[(size_t)r    *32 + kk*8 + tg];
                qf[mi][kk][1] = Qw[(size_t)(r+8)*32 + kk*8 + tg];
                qf[mi][kk][2] = Qw[(size_t)r    *32 + kk*8 + tg + 4];
                qf[mi][kk][3] = Qw[(size_t)(r+8)*32 + kk*8 + tg + 4];
            }
        }
    }

    const int ldrow = t >> 2, lb = (t & 3) * 32;
    uint32_t sK = (uint32_t)__cvta_generic_to_shared(Ks);
    uint32_t sV = (uint32_t)__cvta_generic_to_shared(Vts);
    uint32_t sP = (uint32_t)__cvta_generic_to_shared(Ps);
    const uint32_t stage = 64*KW*4;

    auto issue_kv = [&](int n0, int buf) {
        const char* kg = (const char*)(Kb + (size_t)(n0 + ldrow) * DH) + lb;
        uint32_t dk = sK + buf*stage + ldrow*144 + lb;
        cp16(dk, kg); cp16(dk + 16, kg + 16);
        const char* vg = (const char*)(Vtb + (size_t)ldrow * SL + n0) + lb;
        uint32_t dv = sV + buf*stage + ldrow*144 + lb;
        cp16(dv, vg); cp16(dv + 16, vg + 16);
        cp_commit();
    };

    issue_kv(0, 0);

    float o[2][4][4] = {};
    float l[2][2] = {};

    const int rowB = r8 + selB*8;
    const int colB = selA*4;
    const int rowA = r8 + selA*8;
    const int colA = selB*4;
    const int prow = wm*32 + r8 + selA*8;
    const int pcolS = wn*16 + selB*4;

    for (int n0 = 0; n0 < SL; n0 += 64) {
        const int cur = (n0 >> 6) & 1;
        cp_wait<0>();
        __syncthreads();
        if (n0 + 64 < SL) issue_kv(n0 + 64, cur ^ 1);

        const uint32_t sKc = sK + cur*stage;
        const uint32_t sVc = sV + cur*stage;

        // S = Q K^T  (warp tile 32 x 32)
        float s[2][4][4] = {};
        #pragma unroll
        for (int kk = 0; kk < 4; kk++) {
            #pragma unroll
            for (int nip = 0; nip < 4; nip += 2) {
                uint32_t b0a, b1a, b0b, b1b;
                ldsm4(b0a, b1a, b0b, b1b,
                      sKc + (uint32_t)(((wn*32 + nip*8 + rowB)*KW + kk*8 + colB) * 4));
                #pragma unroll
                for (int mi = 0; mi < 2; mi++) {
                    mma16(s[mi][nip],   qf[mi][kk], b0a, b1a);
                    mma16(s[mi][nip+1], qf[mi][kk], b0b, b1b);
                }
            }
        }

        // P = exp2(S), partial row sums; store P via stmatrix
        #pragma unroll
        for (int mi = 0; mi < 2; mi++) {
            float rs0 = 0.f, rs1 = 0.f;
            #pragma unroll
            for (int ni = 0; ni < 4; ni++) {
                s[mi][ni][0] = exp2f(s[mi][ni][0]); s[mi][ni][1] = exp2f(s[mi][ni][1]);
                s[mi][ni][2] = exp2f(s[mi][ni][2]); s[mi][ni][3] = exp2f(s[mi][ni][3]);
                rs0 += s[mi][ni][0] + s[mi][ni][1];
                rs1 += s[mi][ni][2] + s[mi][ni][3];
            }
            rs0 += __shfl_xor_sync(0xffffffffu, rs0, 1);
            rs0 += __shfl_xor_sync(0xffffffffu, rs0, 2);
            rs1 += __shfl_xor_sync(0xffffffffu, rs1, 1);
            rs1 += __shfl_xor_sync(0xffffffffu, rs1, 2);
            l[mi][0] += rs0; l[mi][1] += rs1;

            #pragma unroll
            for (int nip = 0; nip < 4; nip += 2) {
                stsm4(sP + (uint32_t)(((prow + mi*16)*KW + pcolS + nip*4) * 4),
                      packbf(s[mi][nip][0],   s[mi][nip][1]),
                      packbf(s[mi][nip][2],   s[mi][nip][3]),
                      packbf(s[mi][nip+1][0], s[mi][nip+1][1]),
                      packbf(s[mi][nip+1][2], s[mi][nip+1][3]));
            }
        }
        __syncthreads();

        // O += P V  (warp tile 32 x 32 over d)
        #pragma unroll
        for (int kk = 0; kk < 4; kk++) {
            uint32_t a[2][4];
            #pragma unroll
            for (int mi = 0; mi < 2; mi++)
                ldsm4(a[mi][0], a[mi][1], a[mi][2], a[mi][3],
                      sP + (uint32_t)(((wm*32 + mi*16 + rowA)*KW + kk*8 + colA) * 4));
            #pragma unroll
            for (int nip = 0; nip < 4; nip += 2) {
                uint32_t b0a, b1a, b0b, b1b;
                ldsm4(b0a, b1a, b0b, b1b,
                      sVc + (uint32_t)(((wn*32 + nip*8 + rowB)*KW + kk*8 + colB) * 4));
                #pragma unroll
                for (int mi = 0; mi < 2; mi++) {
                    mma16(o[mi][nip],   a[mi], b0a, b1a);
                    mma16(o[mi][nip+1], a[mi], b0b, b1b);
                }
            }
        }
    }

    // combine row sums across the 2 N-warps
    if (tg == 0) {
        #pragma unroll
        for (int mi = 0; mi < 2; mi++) {
            int pr = wm*32 + mi*16 + g;
            lsum[wn*128 + pr]     = l[mi][0];
            lsum[wn*128 + pr + 8] = l[mi][1];
        }
    }
    __syncthreads();
    {
        const int b = bh >> 2, h = bh & 3;
        #pragma unroll
        for (int mi = 0; mi < 2; mi++) {
            int pr = wm*32 + mi*16 + g;
            float inv0 = 1.0f / (lsum[pr]     + lsum[128 + pr]);
            float inv1 = 1.0f / (lsum[pr + 8] + lsum[128 + pr + 8]);
            size_t r0 = (size_t)(b * SL + m0 + pr) * DM + h * DH;
            size_t r1 = r0 + 8 * DM;
            #pragma unroll
            for (int ni = 0; ni < 4; ni++) {
                int d = wn*32 + ni*8 + 2*tg;
                *(float2*)(ctx + r0 + d) = make_float2(o[mi][ni][0]*inv0, o[mi][ni][1]*inv0);
                *(float2*)(ctx + r1 + d) = make_float2(o[mi][ni][2]*inv1, o[mi][ni][3]*inv1);
            }
        }
    }
}

// ---------------------------------------------------------------------------
// LayerNorm (biased var) + exact GELU, in place on g_ff rows of 512
// ---------------------------------------------------------------------------
__global__ __launch_bounds__(256) void ln_gelu_kernel(const float* __restrict__ g,
                                                      const float* __restrict__ bb)
{
    int row = blockIdx.x;
    float* xr = g_ff + (size_t)row * 512;
    int t = threadIdx.x;
    float v0 = xr[t], v1 = xr[t + 256];
    float sum = v0 + v1;
    float sq  = v0 * v0 + v1 * v1;
    #pragma unroll
    for (int off = 16; off > 0; off >>= 1) {
        sum += __shfl_xor_sync(0xffffffffu, sum, off);
        sq  += __shfl_xor_sync(0xffffffffu, sq,  off);
    }
    __shared__ float ssum[8], ssq[8];
    __shared__ float smean, srstd;
    int w = t >> 5;
    if ((t & 31) == 0) { ssum[w] = sum; ssq[w] = sq; }
    __syncthreads();
    if (t == 0) {
        float S = 0.f, Q = 0.f;
        #pragma unroll
        for (int i = 0; i < 8; i++) { S += ssum[i]; Q += ssq[i]; }
        float mean = S * (1.0f / 512.0f);
        float var  = Q * (1.0f / 512.0f) - mean * mean;
        smean = mean;
        srstd = rsqrtf(var + 1e-5f);
    }
    __syncthreads();
    float mean = smean, rstd = srstd;

    float y0 = (v0 - mean) * rstd * g[t] + bb[t];
    float y1 = (v1 - mean) * rstd * g[t + 256] + bb[t + 256];
    xr[t]       = 0.5f * y0 * (1.0f + erff(y0 * 0.70710678118654752f));
    xr[t + 256] = 0.5f * y1 * (1.0f + erff(y1 * 0.70710678118654752f));
}

// ---------------------------------------------------------------------------
extern "C" void kernel_launch(void* const* d_in, const int* in_sizes, int n_in,
                              void* d_out, int out_size)
{
    (void)in_sizes; (void)n_in; (void)out_size;
    const float* desc   = (const float*)d_in[0];
    const float* kp     = (const float*)d_in[1];
    const float* Wqkv_w = (const float*)d_in[2];
    const float* Wqkv_b = (const float*)d_in[3];
    const float* Wo_w   = (const float*)d_in[4];
    const float* Wo_b   = (const float*)d_in[5];
    const float* W1_w   = (const float*)d_in[6];
    const float* W1_b   = (const float*)d_in[7];
    const float* ln_g   = (const float*)d_in[8];
    const float* ln_b   = (const float*)d_in[9];
    const float* W2_w   = (const float*)d_in[10];
    const float* W2_b   = (const float*)d_in[11];
    float* out = (float*)d_out;

    float *pqkv = nullptr, *pctx = nullptr, *pmsg = nullptr, *pff = nullptr;
    cudaGetSymbolAddress((void**)&pqkv, g_qkv);
    cudaGetSymbolAddress((void**)&pctx, g_ctx);
    cudaGetSymbolAddress((void**)&pmsg, g_msg);
    cudaGetSymbolAddress((void**)&pff,  g_ff);

    cudaFuncSetAttribute(gemm_tc<0, false>, cudaFuncAttributeMaxDynamicSharedMemorySize, GEMM_SMEM);
    cudaFuncSetAttribute(gemm_tc<0, true>,  cudaFuncAttributeMaxDynamicSharedMemorySize, GEMM_SMEM);
    cudaFuncSetAttribute(gemm_tc<2, false>, cudaFuncAttributeMaxDynamicSharedMemorySize, GEMM_SMEM);
    cudaFuncSetAttribute(attn_kernel,       cudaFuncAttributeMaxDynamicSharedMemorySize, ATTN_SMEM);

    // 1. QKV projection
    gemm_tc<0, false><<<dim3(768 / 128, MR / 128), 256, GEMM_SMEM>>>(
        desc, nullptr, Wqkv_w, Wqkv_b, pqkv, nullptr, MR, 768, 256);

    // 2. Repack to bf16 [B,H,S,Dh] + RoPE (+scale on Q)
    repack_rope_kernel<<<(BD * HN * SL * 32) / 256, 256>>>(kp);

    // 2b. V transpose -> [B,H,Dh,S]
    vtrans_kernel<<<dim3(SL / 64, BD * HN), 256>>>();

    // 3. Attention -> ctx [B,S,D]
    attn_kernel<<<dim3(SL / 128, BD * HN), 256, ATTN_SMEM>>>(pctx);

    // 4. message = ctx @ Wo^T + b
    gemm_tc<0, false><<<dim3(DM / 128, MR / 128), 256, GEMM_SMEM>>>(
        pctx, nullptr, Wo_w, Wo_b, pmsg, nullptr, MR, DM, DM);

    // 5. ff = concat(desc, msg) @ W1^T + b
    gemm_tc<0, true><<<dim3(512 / 128, MR / 128), 256, GEMM_SMEM>>>(
        desc, pmsg, W1_w, W1_b, pff, nullptr, MR, 512, 512);

    // 6. LayerNorm + GELU in place
    ln_gelu_kernel<<<MR, 256>>>(ln_g, ln_b);

    // 7. out = desc + ff @ W2^T + b
    gemm_tc<2, false><<<dim3(DM / 128, MR / 128), 256, GEMM_SMEM>>>(
        pff, nullptr, W2_w, W2_b, out, desc, MR, DM, 512);
}

// round 12
// speedup vs baseline: 1.6446x; 1.6446x over previous
#include <cuda_runtime.h>
#include <cuda_bf16.h>
#include <math.h>
#include <stdint.h>

#define BD 8
#define SL 2048
#define DM 256
#define HN 4
#define DH 64
#define MR (BD*SL)   // 16384

// Scratch (device globals; allocation-free per harness rules)
__device__ float g_qkv[MR*768];
__device__ __nv_bfloat16 g_desch[MR*DM];      // bf16 copy of descriptors
__device__ __nv_bfloat16 g_Wqkvh[768*DM];     // bf16 copy of Wqkv_w
__device__ __nv_bfloat16 g_Qh[BD*HN*SL*DH];   // roped, pre-scaled by 0.125*log2(e)
__device__ __nv_bfloat16 g_Kh[BD*HN*SL*DH];   // roped
__device__ __nv_bfloat16 g_Vr[BD*HN*SL*DH];   // row-major [s][d]
__device__ __nv_bfloat16 g_Vt[BD*HN*DH*SL];   // transposed [d][s]
__device__ float g_ctx[MR*DM];
__device__ float g_msg[MR*DM];
__device__ float g_ff[MR*2*DM];

// ---- helpers ----------------------------------------------------------------
__device__ __forceinline__ void mma8(float* c, const uint32_t* a, uint32_t b0, uint32_t b1) {
    asm volatile(
        "mma.sync.aligned.m16n8k8.row.col.f32.tf32.tf32.f32 "
        "{%0,%1,%2,%3},{%4,%5,%6,%7},{%8,%9},{%0,%1,%2,%3};"
        : "+f"(c[0]), "+f"(c[1]), "+f"(c[2]), "+f"(c[3])
        : "r"(a[0]), "r"(a[1]), "r"(a[2]), "r"(a[3]), "r"(b0), "r"(b1));
}
__device__ __forceinline__ void mma16(float* c, const uint32_t* a, uint32_t b0, uint32_t b1) {
    asm volatile(
        "mma.sync.aligned.m16n8k16.row.col.f32.bf16.bf16.f32 "
        "{%0,%1,%2,%3},{%4,%5,%6,%7},{%8,%9},{%0,%1,%2,%3};"
        : "+f"(c[0]), "+f"(c[1]), "+f"(c[2]), "+f"(c[3])
        : "r"(a[0]), "r"(a[1]), "r"(a[2]), "r"(a[3]), "r"(b0), "r"(b1));
}
__device__ __forceinline__ void ldsm4(uint32_t& r0, uint32_t& r1, uint32_t& r2, uint32_t& r3,
                                      uint32_t addr) {
    asm volatile("ldmatrix.sync.aligned.m8n8.x4.shared.b16 {%0,%1,%2,%3}, [%4];"
        : "=r"(r0), "=r"(r1), "=r"(r2), "=r"(r3) : "r"(addr));
}
__device__ __forceinline__ void stsm4(uint32_t addr, uint32_t r0, uint32_t r1,
                                      uint32_t r2, uint32_t r3) {
    asm volatile("stmatrix.sync.aligned.m8n8.x4.shared.b16 [%0], {%1,%2,%3,%4};"
        :: "r"(addr), "r"(r0), "r"(r1), "r"(r2), "r"(r3));
}
__device__ __forceinline__ void cp16(uint32_t saddr, const void* gaddr) {
    asm volatile("cp.async.cg.shared.global [%0], [%1], 16;" :: "r"(saddr), "l"(gaddr));
}
__device__ __forceinline__ void cp_commit() { asm volatile("cp.async.commit_group;"); }
template<int N> __device__ __forceinline__ void cp_wait() {
    asm volatile("cp.async.wait_group %0;" :: "n"(N));
}
__device__ __forceinline__ uint32_t packbf(float a, float b) {
    __nv_bfloat162 h = __floats2bfloat162_rn(a, b);
    return *(uint32_t*)&h;
}

// ---------------------------------------------------------------------------
// fp32 -> bf16 bulk convert (4 elems/thread)
// ---------------------------------------------------------------------------
__global__ __launch_bounds__(256) void f2bf_kernel(const float* __restrict__ src,
                                                   __nv_bfloat16* __restrict__ dst)
{
    int i = (blockIdx.x * blockDim.x + threadIdx.x) * 4;
    float4 v = *(const float4*)(src + i);
    uint2 o;
    o.x = packbf(v.x, v.y);
    o.y = packbf(v.z, v.w);
    *(uint2*)(dst + i) = o;
}

// ---------------------------------------------------------------------------
// bf16 GEMM (m16n8k16 + ldmatrix, cp.async 3-stage): C = A @ W^T + bias (fp32 out)
// BM=128, BN=128, BK=32. 8 warps (4M x 2N), warp tile 32x64.
// Used for QKV only (error washes through softmax).
// ---------------------------------------------------------------------------
#define HST 20   // smem row stride in 4B words per 32-bf16 row-chunk
#define GEMMH_SMEM (3*256*HST*4)   // 61440 bytes
__global__ __launch_bounds__(256) void gemm_bf16(
    const __nv_bfloat16* __restrict__ A, const __nv_bfloat16* __restrict__ W,
    const float* __restrict__ bias, float* __restrict__ C,
    int M, int N, int K)
{
    extern __shared__ uint32_t hsm[];
    const int t = threadIdx.x;
    const int w = t >> 5, wm = w & 3, wn = w >> 2;
    const int lane = t & 31, g4 = lane >> 2, tg = lane & 3;
    const int r8 = lane & 7;
    const int selA = (lane >> 3) & 1;
    const int selB = (lane >> 4) & 1;
    const int m0 = blockIdx.y << 7, n0 = blockIdx.x << 7;

    float acc[2][8][4] = {};

    uint32_t sS = (uint32_t)__cvta_generic_to_shared(hsm);
    const uint32_t stg = 256*HST*4;   // rows 0-127: A, 128-255: B

    auto issue = [&](int k0, int buf) {
        const __nv_bfloat16* src = (t < 128) ? (A + (size_t)(m0 + t) * K + k0)
                                             : (W + (size_t)(n0 + t - 128) * K + k0);
        uint32_t d = sS + buf*stg + t*HST*4;
        cp16(d, src); cp16(d + 16, src + 8); cp16(d + 32, src + 16); cp16(d + 48, src + 24);
        cp_commit();
    };

    issue(0, 0);
    issue(32, 1);

    const int niters = K >> 5;
    int cur = 0;
    for (int it = 0; it < niters; it++) {
        cp_wait<1>();
        __syncthreads();
        if (it + 2 < niters) issue((it + 2) << 5, (it + 2) % 3);

        const uint32_t base = sS + cur*stg;
        #pragma unroll
        for (int ks = 0; ks < 2; ks++) {
            uint32_t a[2][4];
            #pragma unroll
            for (int mi = 0; mi < 2; mi++)
                ldsm4(a[mi][0], a[mi][1], a[mi][2], a[mi][3],
                      base + (uint32_t)(((wm*32 + mi*16 + r8 + selA*8)*HST + ks*8 + selB*4) * 4));
            #pragma unroll
            for (int nip = 0; nip < 8; nip += 2) {
                uint32_t b0a, b1a, b0b, b1b;
                ldsm4(b0a, b1a, b0b, b1b,
                      base + (uint32_t)(((128 + wn*64 + nip*8 + r8 + selB*8)*HST + ks*8 + selA*4) * 4));
                mma16(acc[0][nip],   a[0], b0a, b1a);
                mma16(acc[1][nip],   a[1], b0a, b1a);
                mma16(acc[0][nip+1], a[0], b0b, b1b);
                mma16(acc[1][nip+1], a[1], b0b, b1b);
            }
        }
        __syncthreads();
        cur = (cur + 1 == 3) ? 0 : cur + 1;
    }

    #pragma unroll
    for (int mi = 0; mi < 2; mi++) {
        #pragma unroll
        for (int ni = 0; ni < 8; ni++) {
            int gm = m0 + wm*32 + mi*16 + g4;
            int gn = n0 + wn*64 + ni*8 + 2*tg;
            float b0 = bias[gn], b1 = bias[gn+1];
            *(float2*)(C + (size_t)gm * N + gn) =
                make_float2(acc[mi][ni][0] + b0, acc[mi][ni][1] + b1);
            *(float2*)(C + (size_t)(gm+8) * N + gn) =
                make_float2(acc[mi][ni][2] + b0, acc[mi][ni][3] + b1);
        }
    }
}

// ---------------------------------------------------------------------------
// Tensor-core GEMM (TF32, cp.async 3-stage, dynamic smem): C = A @ W^T + bias.
// BM=128, BN=128, BK=16. 8 warps (4M x 2N), warp tile 32x64.
// ---------------------------------------------------------------------------
#define AST 20
#define GEMM_SMEM (3*2*128*AST*4)   // 61440 bytes
template<int MODE, bool CONCAT>
__global__ __launch_bounds__(256) void gemm_tc(
    const float* __restrict__ A, const float* __restrict__ A2,
    const float* __restrict__ W, const float* __restrict__ bias,
    float* __restrict__ C, const float* __restrict__ res,
    int M, int N, int K)
{
    extern __shared__ float dsm[];
    float* Asm = dsm;
    float* Bsm = dsm + 3*128*AST;
    const int t = threadIdx.x;
    const int w = t >> 5, wm = w & 3, wn = w >> 2;
    const int lane = t & 31, lr4 = lane >> 2, lc4 = lane & 3;
    const int m0 = blockIdx.y << 7, n0 = blockIdx.x << 7;

    float acc[2][8][4] = {};

    const int ldr = t >> 1;
    const int ldc = (t & 1) << 3;

    uint32_t sA = (uint32_t)__cvta_generic_to_shared(Asm);
    uint32_t sB = (uint32_t)__cvta_generic_to_shared(Bsm);
    const uint32_t stg = 128*AST*4;

    auto issue_stage = [&](int k0, int buf) {
        int kk = k0 + ldc;
        const float* asrc;
        if (CONCAT) asrc = (kk >= 256) ? (A2 + (size_t)(m0 + ldr) * 256 + kk - 256)
                                       : (A  + (size_t)(m0 + ldr) * 256 + kk);
        else        asrc = A + (size_t)(m0 + ldr) * K + kk;
        uint32_t da = sA + buf*stg + (ldr*AST + ldc)*4;
        cp16(da,      asrc);
        cp16(da + 16, asrc + 4);
        const float* bsrc = W + (size_t)(n0 + ldr) * K + k0 + ldc;
        uint32_t db = sB + buf*stg + (ldr*AST + ldc)*4;
        cp16(db,      bsrc);
        cp16(db + 16, bsrc + 4);
        cp_commit();
    };

    issue_stage(0, 0);
    issue_stage(16, 1);

    const int niters = K >> 4;
    int cur = 0;
    for (int it = 0; it < niters; it++) {
        cp_wait<1>();
        __syncthreads();
        if (it + 2 < niters) issue_stage((it + 2) << 4, (it + 2) % 3);

        const uint32_t* Ac = (const uint32_t*)(Asm + cur*128*AST);
        const uint32_t* Bc = (const uint32_t*)(Bsm + cur*128*AST);
        #pragma unroll
        for (int ks = 0; ks < 2; ks++) {
            const int kb = ks << 3;
            uint32_t a[2][4];
            #pragma unroll
            for (int mi = 0; mi < 2; mi++) {
                int r = wm*32 + mi*16 + lr4, c = kb + lc4;
                a[mi][0] = Ac[r*AST + c];     a[mi][1] = Ac[(r+8)*AST + c];
                a[mi][2] = Ac[r*AST + c + 4]; a[mi][3] = Ac[(r+8)*AST + c + 4];
            }
            #pragma unroll
            for (int ni = 0; ni < 8; ni++) {
                int r = wn*64 + ni*8 + lr4, c = kb + lc4;
                uint32_t b0 = Bc[r*AST + c], b1 = Bc[r*AST + c + 4];
                mma8(acc[0][ni], a[0], b0, b1);
                mma8(acc[1][ni], a[1], b0, b1);
            }
        }
        __syncthreads();
        cur = (cur + 1 == 3) ? 0 : cur + 1;
    }

    #pragma unroll
    for (int mi = 0; mi < 2; mi++) {
        #pragma unroll
        for (int ni = 0; ni < 8; ni++) {
            int gm = m0 + wm*32 + mi*16 + lr4;
            int gn = n0 + wn*64 + ni*8 + 2*lc4;
            float b0 = bias[gn], b1 = bias[gn+1];
            float v00 = acc[mi][ni][0] + b0, v01 = acc[mi][ni][1] + b1;
            float v10 = acc[mi][ni][2] + b0, v11 = acc[mi][ni][3] + b1;
            if (MODE == 2) {
                const float* r0 = res + (size_t)gm * N + gn;
                const float* r1 = res + (size_t)(gm+8) * N + gn;
                v00 += r0[0]; v01 += r0[1]; v10 += r1[0]; v11 += r1[1];
            }
            *(float2*)(C + (size_t)gm * N + gn)     = make_float2(v00, v01);
            *(float2*)(C + (size_t)(gm+8) * N + gn) = make_float2(v10, v11);
        }
    }
}

// ---------------------------------------------------------------------------
// Repack qkv [M,768] -> bf16 Q (roped + scaled by 0.125*log2e), K (roped), V.
// ---------------------------------------------------------------------------
__global__ __launch_bounds__(256) void repack_rope_kernel(const float* __restrict__ kp)
{
    int idx = blockIdx.x * blockDim.x + threadIdx.x;   // B*H*S*32 pairs
    int d2 = idx & 31;
    int s  = (idx >> 5) & (SL - 1);
    int h  = (idx >> 16) & (HN - 1);
    int b  = idx >> 18;

    int gm = b * SL + s;
    const float* src = g_qkv + (size_t)gm * 768 + h * 192 + 6 * d2;
    float q0 = src[0], k0 = src[1], v0 = src[2];
    float q1 = src[3], k1 = src[4], v1 = src[5];

    const int SIN_OFF = BD * SL * DH;
    int kb = (b * SL + s) * DH + (d2 << 1);
    float c0 = kp[kb],           c1 = kp[kb + 1];
    float s0 = kp[SIN_OFF + kb], s1 = kp[SIN_OFF + kb + 1];

    int base = (((b * HN + h) * SL) + s) * DH + (d2 << 1);
    const float scale = 0.125f * 1.4426950408889634f;   // Dh^-0.5 * log2(e)
    *(__nv_bfloat162*)&g_Qh[base] =
        __floats2bfloat162_rn((q0*c0 - q1*s0)*scale, (q1*c1 + q0*s1)*scale);
    *(__nv_bfloat162*)&g_Kh[base] =
        __floats2bfloat162_rn(k0*c0 - k1*s0, k1*c1 + k0*s1);
    *(__nv_bfloat162*)&g_Vr[base] = __floats2bfloat162_rn(v0, v1);
}

// ---------------------------------------------------------------------------
// V transpose: g_Vr [bh][s][d] -> g_Vt [bh][d][s], 64x64 smem tiles
// ---------------------------------------------------------------------------
__global__ __launch_bounds__(256) void vtrans_kernel()
{
    __shared__ uint32_t tile[64*33];
    const int t = threadIdx.x;
    const int bh = blockIdx.y;
    const int s0 = blockIdx.x << 6;

    {
        int sr = t >> 2, wc = (t & 3) * 8;
        const uint32_t* src = (const uint32_t*)(g_Vr + (size_t)bh*SL*DH + (size_t)(s0+sr)*DH) + wc;
        #pragma unroll
        for (int i = 0; i < 8; i++) tile[sr*33 + wc + i] = src[i];
    }
    __syncthreads();
    {
        int d = t >> 2, sc = (t & 3) * 16;
        uint32_t outw[8];
        #pragma unroll
        for (int j = 0; j < 8; j++) {
            uint32_t w0 = tile[(sc + 2*j    )*33 + (d >> 1)];
            uint32_t w1 = tile[(sc + 2*j + 1)*33 + (d >> 1)];
            uint32_t lo = (d & 1) ? (w0 >> 16) : (w0 & 0xffffu);
            uint32_t hi = (d & 1) ? (w1 >> 16) : (w1 & 0xffffu);
            outw[j] = lo | (hi << 16);
        }
        uint32_t* dst = (uint32_t*)(g_Vt + (size_t)bh*DH*SL + (size_t)d*SL + s0 + sc);
        *(uint4*)dst       = make_uint4(outw[0], outw[1], outw[2], outw[3]);
        *(uint4*)(dst + 4) = make_uint4(outw[4], outw[5], outw[6], outw[7]);
    }
}

// ---------------------------------------------------------------------------
// Flash attention (R10 config), bf16 m16n8k16 + ldmatrix/stmatrix, exp2 softmax,
// cp.async 2-stage K/V. CTA: 64 queries x 64-key tiles. 8 warps: 4(M) x 2(N).
// ---------------------------------------------------------------------------
#define KW 36   // smem row stride in 4B words (72 bf16)
__global__ __launch_bounds__(256) void attn_kernel(float* __restrict__ ctx)
{
    __shared__ uint32_t Ks[2][64*KW];
    __shared__ uint32_t Vts[2][64*KW];
    __shared__ uint32_t Ps[64*KW];
    __shared__ float lsum[2][64];

    const int t = threadIdx.x;
    const int w = t >> 5, wm = w & 3, wn = w >> 2;
    const int lane = t & 31, g = lane >> 2, tg = lane & 3;
    const int r8 = lane & 7;
    const int selA = (lane >> 3) & 1;
    const int selB = (lane >> 4) & 1;
    const int bh = blockIdx.y;
    const int m0 = blockIdx.x << 6;

    const __nv_bfloat16* Qb  = g_Qh + (size_t)bh * SL * DH;
    const __nv_bfloat16* Kb  = g_Kh + (size_t)bh * SL * DH;
    const __nv_bfloat16* Vtb = g_Vt + (size_t)bh * DH * SL;

    // Q fragments in registers: 4 k-steps x 4 regs (bf16 pairs)
    uint32_t qf[4][4];
    {
        const uint32_t* Qw = (const uint32_t*)Qb;   // 32 words per row
        int r = m0 + wm*16 + g;
        #pragma unroll
        for (int kk = 0; kk < 4; kk++) {
            qf[kk][0] = Qw[(size_t)r    *32 + kk*8 + tg];
            qf[kk][1] = Qw[(size_t)(r+8)*32 + kk*8 + tg];
            qf[kk][2] = Qw[(size_t)r    *32 + kk*8 + tg + 4];
            qf[kk][3] = Qw[(size_t)(r+8)*32 + kk*8 + tg + 4];
        }
    }

    const int ldrow = t >> 2, lb = (t & 3) * 32;
    uint32_t sK = (uint32_t)__cvta_generic_to_shared(&Ks[0][0]);
    uint32_t sV = (uint32_t)__cvta_generic_to_shared(&Vts[0][0]);
    uint32_t sP = (uint32_t)__cvta_generic_to_shared(&Ps[0]);
    const uint32_t stage = 64*KW*4;

    auto issue_kv = [&](int n0, int buf) {
        const char* kg = (const char*)(Kb + (size_t)(n0 + ldrow) * DH) + lb;
        uint32_t dk = sK + buf*stage + ldrow*144 + lb;
        cp16(dk, kg); cp16(dk + 16, kg + 16);
        const char* vg = (const char*)(Vtb + (size_t)ldrow * SL + n0) + lb;
        uint32_t dv = sV + buf*stage + ldrow*144 + lb;
        cp16(dv, vg); cp16(dv + 16, vg + 16);
        cp_commit();
    };

    issue_kv(0, 0);

    float o[4][4] = {};
    float l0 = 0.f, l1 = 0.f;

    const int rowB = r8 + selB*8;
    const int colB = selA*4;
    const int rowA = r8 + selA*8;
    const int colA = selB*4;
    const int prow = wm*16 + r8 + selA*8;
    const int pcolS = wn*16 + selB*4;

    for (int n0 = 0; n0 < SL; n0 += 64) {
        const int cur = (n0 >> 6) & 1;
        cp_wait<0>();
        __syncthreads();
        if (n0 + 64 < SL) issue_kv(n0 + 64, cur ^ 1);

        const uint32_t sKc = sK + cur*stage;
        const uint32_t sVc = sV + cur*stage;

        // S = Q K^T  (warp tile 16 x 32)
        float s[4][4] = {};
        #pragma unroll
        for (int kk = 0; kk < 4; kk++) {
            #pragma unroll
            for (int nip = 0; nip < 4; nip += 2) {
                uint32_t b0a, b1a, b0b, b1b;
                ldsm4(b0a, b1a, b0b, b1b,
                      sKc + (uint32_t)(((wn*32 + nip*8 + rowB)*KW + kk*8 + colB) * 4));
                mma16(s[nip],   qf[kk], b0a, b1a);
                mma16(s[nip+1], qf[kk], b0b, b1b);
            }
        }

        // P = exp2(S), partial row sums
        float rs0 = 0.f, rs1 = 0.f;
        #pragma unroll
        for (int ni = 0; ni < 4; ni++) {
            s[ni][0] = exp2f(s[ni][0]); s[ni][1] = exp2f(s[ni][1]);
            s[ni][2] = exp2f(s[ni][2]); s[ni][3] = exp2f(s[ni][3]);
            rs0 += s[ni][0] + s[ni][1];
            rs1 += s[ni][2] + s[ni][3];
        }
        rs0 += __shfl_xor_sync(0xffffffffu, rs0, 1);
        rs0 += __shfl_xor_sync(0xffffffffu, rs0, 2);
        rs1 += __shfl_xor_sync(0xffffffffu, rs1, 1);
        rs1 += __shfl_xor_sync(0xffffffffu, rs1, 2);
        l0 += rs0; l1 += rs1;

        // store P via stmatrix (bf16 pairs)
        #pragma unroll
        for (int nip = 0; nip < 4; nip += 2) {
            stsm4(sP + (uint32_t)((prow*KW + pcolS + nip*4) * 4),
                  packbf(s[nip][0],   s[nip][1]),   packbf(s[nip][2],   s[nip][3]),
                  packbf(s[nip+1][0], s[nip+1][1]), packbf(s[nip+1][2], s[nip+1][3]));
        }
        __syncthreads();

        // O += P V  (warp tile 16 x 32 over d)
        #pragma unroll
        for (int kk = 0; kk < 4; kk++) {
            uint32_t a[4];
            ldsm4(a[0], a[1], a[2], a[3],
                  sP + (uint32_t)(((wm*16 + rowA)*KW + kk*8 + colA) * 4));
            #pragma unroll
            for (int nip = 0; nip < 4; nip += 2) {
                uint32_t b0a, b1a, b0b, b1b;
                ldsm4(b0a, b1a, b0b, b1b,
                      sVc + (uint32_t)(((wn*32 + nip*8 + rowB)*KW + kk*8 + colB) * 4));
                mma16(o[nip],   a, b0a, b1a);
                mma16(o[nip+1], a, b0b, b1b);
            }
        }
    }

    // combine row sums across the 2 N-warps
    {
        int pr = wm*16 + g;
        if (tg == 0) { lsum[wn][pr] = l0; lsum[wn][pr + 8] = l1; }
    }
    __syncthreads();
    {
        int pr = wm*16 + g;
        float inv0 = 1.0f / (lsum[0][pr]     + lsum[1][pr]);
        float inv1 = 1.0f / (lsum[0][pr + 8] + lsum[1][pr + 8]);
        const int b = bh >> 2, h = bh & 3;
        size_t r0 = (size_t)(b * SL + m0 + pr) * DM + h * DH;
        size_t r1 = r0 + 8 * DM;
        #pragma unroll
        for (int ni = 0; ni < 4; ni++) {
            int d = wn*32 + ni*8 + 2*tg;
            *(float2*)(ctx + r0 + d) = make_float2(o[ni][0]*inv0, o[ni][1]*inv0);
            *(float2*)(ctx + r1 + d) = make_float2(o[ni][2]*inv1, o[ni][3]*inv1);
        }
    }
}

// ---------------------------------------------------------------------------
// LayerNorm (biased var) + exact GELU, in place on g_ff rows of 512
// ---------------------------------------------------------------------------
__global__ __launch_bounds__(256) void ln_gelu_kernel(const float* __restrict__ g,
                                                      const float* __restrict__ bb)
{
    int row = blockIdx.x;
    float* xr = g_ff + (size_t)row * 512;
    int t = threadIdx.x;
    float v0 = xr[t], v1 = xr[t + 256];
    float sum = v0 + v1;
    float sq  = v0 * v0 + v1 * v1;
    #pragma unroll
    for (int off = 16; off > 0; off >>= 1) {
        sum += __shfl_xor_sync(0xffffffffu, sum, off);
        sq  += __shfl_xor_sync(0xffffffffu, sq,  off);
    }
    __shared__ float ssum[8], ssq[8];
    __shared__ float smean, srstd;
    int w = t >> 5;
    if ((t & 31) == 0) { ssum[w] = sum; ssq[w] = sq; }
    __syncthreads();
    if (t == 0) {
        float S = 0.f, Q = 0.f;
        #pragma unroll
        for (int i = 0; i < 8; i++) { S += ssum[i]; Q += ssq[i]; }
        float mean = S * (1.0f / 512.0f);
        float var  = Q * (1.0f / 512.0f) - mean * mean;
        smean = mean;
        srstd = rsqrtf(var + 1e-5f);
    }
    __syncthreads();
    float mean = smean, rstd = srstd;

    float y0 = (v0 - mean) * rstd * g[t] + bb[t];
    float y1 = (v1 - mean) * rstd * g[t + 256] + bb[t + 256];
    xr[t]       = 0.5f * y0 * (1.0f + erff(y0 * 0.70710678118654752f));
    xr[t + 256] = 0.5f * y1 * (1.0f + erff(y1 * 0.70710678118654752f));
}

// ---------------------------------------------------------------------------
extern "C" void kernel_launch(void* const* d_in, const int* in_sizes, int n_in,
                              void* d_out, int out_size)
{
    (void)in_sizes; (void)n_in; (void)out_size;
    const float* desc   = (const float*)d_in[0];
    const float* kp     = (const float*)d_in[1];
    const float* Wqkv_w = (const float*)d_in[2];
    const float* Wqkv_b = (const float*)d_in[3];
    const float* Wo_w   = (const float*)d_in[4];
    const float* Wo_b   = (const float*)d_in[5];
    const float* W1_w   = (const float*)d_in[6];
    const float* W1_b   = (const float*)d_in[7];
    const float* ln_g   = (const float*)d_in[8];
    const float* ln_b   = (const float*)d_in[9];
    const float* W2_w   = (const float*)d_in[10];
    const float* W2_b   = (const float*)d_in[11];
    float* out = (float*)d_out;

    float *pqkv = nullptr, *pctx = nullptr, *pmsg = nullptr, *pff = nullptr;
    __nv_bfloat16 *pdesch = nullptr, *pWh = nullptr;
    cudaGetSymbolAddress((void**)&pqkv, g_qkv);
    cudaGetSymbolAddress((void**)&pctx, g_ctx);
    cudaGetSymbolAddress((void**)&pmsg, g_msg);
    cudaGetSymbolAddress((void**)&pff,  g_ff);
    cudaGetSymbolAddress((void**)&pdesch, g_desch);
    cudaGetSymbolAddress((void**)&pWh,    g_Wqkvh);

    cudaFuncSetAttribute(gemm_tc<0, false>, cudaFuncAttributeMaxDynamicSharedMemorySize, GEMM_SMEM);
    cudaFuncSetAttribute(gemm_tc<0, true>,  cudaFuncAttributeMaxDynamicSharedMemorySize, GEMM_SMEM);
    cudaFuncSetAttribute(gemm_tc<2, false>, cudaFuncAttributeMaxDynamicSharedMemorySize, GEMM_SMEM);
    cudaFuncSetAttribute(gemm_bf16,         cudaFuncAttributeMaxDynamicSharedMemorySize, GEMMH_SMEM);

    // 0. bf16 copies of desc and Wqkv_w
    f2bf_kernel<<<(MR * DM) / 1024, 256>>>(desc, pdesch);
    f2bf_kernel<<<(768 * DM) / 1024, 256>>>(Wqkv_w, pWh);

    // 1. QKV projection (bf16 tensor cores)
    gemm_bf16<<<dim3(768 / 128, MR / 128), 256, GEMMH_SMEM>>>(
        pdesch, pWh, Wqkv_b, pqkv, MR, 768, 256);

    // 2. Repack to bf16 [B,H,S,Dh] + RoPE (+scale on Q)
    repack_rope_kernel<<<(BD * HN * SL * 32) / 256, 256>>>(kp);

    // 2b. V transpose -> [B,H,Dh,S]
    vtrans_kernel<<<dim3(SL / 64, BD * HN), 256>>>();

    // 3. Attention -> ctx [B,S,D]
    attn_kernel<<<dim3(SL / 64, BD * HN), 256>>>(pctx);

    // 4. message = ctx @ Wo^T + b
    gemm_tc<0, false><<<dim3(DM / 128, MR / 128), 256, GEMM_SMEM>>>(
        pctx, nullptr, Wo_w, Wo_b, pmsg, nullptr, MR, DM, DM);

    // 5. ff = concat(desc, msg) @ W1^T + b
    gemm_tc<0, true><<<dim3(512 / 128, MR / 128), 256, GEMM_SMEM>>>(
        desc, pmsg, W1_w, W1_b, pff, nullptr, MR, 512, 512);

    // 6. LayerNorm + GELU in place
    ln_gelu_kernel<<<MR, 256>>>(ln_g, ln_b);

    // 7. out = desc + ff @ W2^T + b
    gemm_tc<2, false><<<dim3(DM / 128, MR / 128), 256, GEMM_SMEM>>>(
        pff, nullptr, W2_w, W2_b, out, desc, MR, DM, 512);
}

// round 14
// speedup vs baseline: 1.7522x; 1.0654x over previous
#include <cuda_runtime.h>
#include <cuda_bf16.h>
#include <math.h>
#include <stdint.h>

#define BD 8
#define SL 2048
#define DM 256
#define HN 4
#define DH 64
#define MR (BD*SL)   // 16384

// Scratch (device globals; allocation-free per harness rules)
__device__ float g_qkv[MR*768];
__device__ __nv_bfloat16 g_desch[MR*DM];      // bf16 copy of descriptors
__device__ __nv_bfloat16 g_Wqkvh[768*DM];     // bf16 copy of Wqkv_w
__device__ __nv_bfloat16 g_Woh[DM*DM];        // bf16 copy of Wo_w
__device__ __nv_bfloat16 g_Qh[BD*HN*SL*DH];   // roped, pre-scaled by 0.125*log2(e)
__device__ __nv_bfloat16 g_Kh[BD*HN*SL*DH];   // roped
__device__ __nv_bfloat16 g_Vr[BD*HN*SL*DH];   // row-major [s][d]
__device__ __nv_bfloat16 g_Vt[BD*HN*DH*SL];   // transposed [d][s]
__device__ __nv_bfloat16 g_ctxh[MR*DM];       // attention output, bf16
__device__ float g_msg[MR*DM];
__device__ float g_ff[MR*2*DM];

// ---- helpers ----------------------------------------------------------------
__device__ __forceinline__ void mma8(float* c, const uint32_t* a, uint32_t b0, uint32_t b1) {
    asm volatile(
        "mma.sync.aligned.m16n8k8.row.col.f32.tf32.tf32.f32 "
        "{%0,%1,%2,%3},{%4,%5,%6,%7},{%8,%9},{%0,%1,%2,%3};"
        : "+f"(c[0]), "+f"(c[1]), "+f"(c[2]), "+f"(c[3])
        : "r"(a[0]), "r"(a[1]), "r"(a[2]), "r"(a[3]), "r"(b0), "r"(b1));
}
__device__ __forceinline__ void mma16(float* c, const uint32_t* a, uint32_t b0, uint32_t b1) {
    asm volatile(
        "mma.sync.aligned.m16n8k16.row.col.f32.bf16.bf16.f32 "
        "{%0,%1,%2,%3},{%4,%5,%6,%7},{%8,%9},{%0,%1,%2,%3};"
        : "+f"(c[0]), "+f"(c[1]), "+f"(c[2]), "+f"(c[3])
        : "r"(a[0]), "r"(a[1]), "r"(a[2]), "r"(a[3]), "r"(b0), "r"(b1));
}
__device__ __forceinline__ void ldsm4(uint32_t& r0, uint32_t& r1, uint32_t& r2, uint32_t& r3,
                                      uint32_t addr) {
    asm volatile("ldmatrix.sync.aligned.m8n8.x4.shared.b16 {%0,%1,%2,%3}, [%4];"
        : "=r"(r0), "=r"(r1), "=r"(r2), "=r"(r3) : "r"(addr));
}
__device__ __forceinline__ void cp16(uint32_t saddr, const void* gaddr) {
    asm volatile("cp.async.cg.shared.global [%0], [%1], 16;" :: "r"(saddr), "l"(gaddr));
}
__device__ __forceinline__ void cp_commit() { asm volatile("cp.async.commit_group;"); }
template<int N> __device__ __forceinline__ void cp_wait() {
    asm volatile("cp.async.wait_group %0;" :: "n"(N));
}
__device__ __forceinline__ uint32_t packbf(float a, float b) {
    __nv_bfloat162 h = __floats2bfloat162_rn(a, b);
    return *(uint32_t*)&h;
}

// ---------------------------------------------------------------------------
// fp32 -> bf16 bulk convert (4 elems/thread)
// ---------------------------------------------------------------------------
__global__ __launch_bounds__(256) void f2bf_kernel(const float* __restrict__ src,
                                                   __nv_bfloat16* __restrict__ dst)
{
    int i = (blockIdx.x * blockDim.x + threadIdx.x) * 4;
    float4 v = *(const float4*)(src + i);
    uint2 o;
    o.x = packbf(v.x, v.y);
    o.y = packbf(v.z, v.w);
    *(uint2*)(dst + i) = o;
}

// ---------------------------------------------------------------------------
// bf16 GEMM (m16n8k16 + ldmatrix, cp.async 3-stage): C = A @ W^T + bias (fp32 out)
// BM=128, BN=128, BK=32. 8 warps (4M x 2N), warp tile 32x64.
// ---------------------------------------------------------------------------
#define HST 20   // smem row stride in 4B words per 32-bf16 row-chunk
#define GEMMH_SMEM (3*256*HST*4)   // 61440 bytes
__global__ __launch_bounds__(256) void gemm_bf16(
    const __nv_bfloat16* __restrict__ A, const __nv_bfloat16* __restrict__ W,
    const float* __restrict__ bias, float* __restrict__ C,
    int M, int N, int K)
{
    extern __shared__ uint32_t hsm[];
    const int t = threadIdx.x;
    const int w = t >> 5, wm = w & 3, wn = w >> 2;
    const int lane = t & 31, g4 = lane >> 2, tg = lane & 3;
    const int r8 = lane & 7;
    const int selA = (lane >> 3) & 1;
    const int selB = (lane >> 4) & 1;
    const int m0 = blockIdx.y << 7, n0 = blockIdx.x << 7;

    float acc[2][8][4] = {};

    uint32_t sS = (uint32_t)__cvta_generic_to_shared(hsm);
    const uint32_t stg = 256*HST*4;   // rows 0-127: A, 128-255: B

    auto issue = [&](int k0, int buf) {
        const __nv_bfloat16* src = (t < 128) ? (A + (size_t)(m0 + t) * K + k0)
                                             : (W + (size_t)(n0 + t - 128) * K + k0);
        uint32_t d = sS + buf*stg + t*HST*4;
        cp16(d, src); cp16(d + 16, src + 8); cp16(d + 32, src + 16); cp16(d + 48, src + 24);
        cp_commit();
    };

    issue(0, 0);
    issue(32, 1);

    const int niters = K >> 5;
    int cur = 0;
    for (int it = 0; it < niters; it++) {
        cp_wait<1>();
        __syncthreads();
        if (it + 2 < niters) issue((it + 2) << 5, (it + 2) % 3);

        const uint32_t base = sS + cur*stg;
        #pragma unroll
        for (int ks = 0; ks < 2; ks++) {
            uint32_t a[2][4];
            #pragma unroll
            for (int mi = 0; mi < 2; mi++)
                ldsm4(a[mi][0], a[mi][1], a[mi][2], a[mi][3],
                      base + (uint32_t)(((wm*32 + mi*16 + r8 + selA*8)*HST + ks*8 + selB*4) * 4));
            #pragma unroll
            for (int nip = 0; nip < 8; nip += 2) {
                uint32_t b0a, b1a, b0b, b1b;
                ldsm4(b0a, b1a, b0b, b1b,
                      base + (uint32_t)(((128 + wn*64 + nip*8 + r8 + selB*8)*HST + ks*8 + selA*4) * 4));
                mma16(acc[0][nip],   a[0], b0a, b1a);
                mma16(acc[1][nip],   a[1], b0a, b1a);
                mma16(acc[0][nip+1], a[0], b0b, b1b);
                mma16(acc[1][nip+1], a[1], b0b, b1b);
            }
        }
        __syncthreads();
        cur = (cur + 1 == 3) ? 0 : cur + 1;
    }

    #pragma unroll
    for (int mi = 0; mi < 2; mi++) {
        #pragma unroll
        for (int ni = 0; ni < 8; ni++) {
            int gm = m0 + wm*32 + mi*16 + g4;
            int gn = n0 + wn*64 + ni*8 + 2*tg;
            float b0 = bias[gn], b1 = bias[gn+1];
            *(float2*)(C + (size_t)gm * N + gn) =
                make_float2(acc[mi][ni][0] + b0, acc[mi][ni][1] + b1);
            *(float2*)(C + (size_t)(gm+8) * N + gn) =
                make_float2(acc[mi][ni][2] + b0, acc[mi][ni][3] + b1);
        }
    }
}

// ---------------------------------------------------------------------------
// Tensor-core GEMM (TF32, cp.async 3-stage, dynamic smem): C = A @ W^T + bias.
// BM=128, BN=128, BK=16. 8 warps (4M x 2N), warp tile 32x64.
// ---------------------------------------------------------------------------
#define AST 20
#define GEMM_SMEM (3*2*128*AST*4)   // 61440 bytes
template<int MODE, bool CONCAT>
__global__ __launch_bounds__(256) void gemm_tc(
    const float* __restrict__ A, const float* __restrict__ A2,
    const float* __restrict__ W, const float* __restrict__ bias,
    float* __restrict__ C, const float* __restrict__ res,
    int M, int N, int K)
{
    extern __shared__ float dsm[];
    float* Asm = dsm;
    float* Bsm = dsm + 3*128*AST;
    const int t = threadIdx.x;
    const int w = t >> 5, wm = w & 3, wn = w >> 2;
    const int lane = t & 31, lr4 = lane >> 2, lc4 = lane & 3;
    const int m0 = blockIdx.y << 7, n0 = blockIdx.x << 7;

    float acc[2][8][4] = {};

    const int ldr = t >> 1;
    const int ldc = (t & 1) << 3;

    uint32_t sA = (uint32_t)__cvta_generic_to_shared(Asm);
    uint32_t sB = (uint32_t)__cvta_generic_to_shared(Bsm);
    const uint32_t stg = 128*AST*4;

    auto issue_stage = [&](int k0, int buf) {
        int kk = k0 + ldc;
        const float* asrc;
        if (CONCAT) asrc = (kk >= 256) ? (A2 + (size_t)(m0 + ldr) * 256 + kk - 256)
                                       : (A  + (size_t)(m0 + ldr) * 256 + kk);
        else        asrc = A + (size_t)(m0 + ldr) * K + kk;
        uint32_t da = sA + buf*stg + (ldr*AST + ldc)*4;
        cp16(da,      asrc);
        cp16(da + 16, asrc + 4);
        const float* bsrc = W + (size_t)(n0 + ldr) * K + k0 + ldc;
        uint32_t db = sB + buf*stg + (ldr*AST + ldc)*4;
        cp16(db,      bsrc);
        cp16(db + 16, bsrc + 4);
        cp_commit();
    };

    issue_stage(0, 0);
    issue_stage(16, 1);

    const int niters = K >> 4;
    int cur = 0;
    for (int it = 0; it < niters; it++) {
        cp_wait<1>();
        __syncthreads();
        if (it + 2 < niters) issue_stage((it + 2) << 4, (it + 2) % 3);

        const uint32_t* Ac = (const uint32_t*)(Asm + cur*128*AST);
        const uint32_t* Bc = (const uint32_t*)(Bsm + cur*128*AST);
        #pragma unroll
        for (int ks = 0; ks < 2; ks++) {
            const int kb = ks << 3;
            uint32_t a[2][4];
            #pragma unroll
            for (int mi = 0; mi < 2; mi++) {
                int r = wm*32 + mi*16 + lr4, c = kb + lc4;
                a[mi][0] = Ac[r*AST + c];     a[mi][1] = Ac[(r+8)*AST + c];
                a[mi][2] = Ac[r*AST + c + 4]; a[mi][3] = Ac[(r+8)*AST + c + 4];
            }
            #pragma unroll
            for (int ni = 0; ni < 8; ni++) {
                int r = wn*64 + ni*8 + lr4, c = kb + lc4;
                uint32_t b0 = Bc[r*AST + c], b1 = Bc[r*AST + c + 4];
                mma8(acc[0][ni], a[0], b0, b1);
                mma8(acc[1][ni], a[1], b0, b1);
            }
        }
        __syncthreads();
        cur = (cur + 1 == 3) ? 0 : cur + 1;
    }

    #pragma unroll
    for (int mi = 0; mi < 2; mi++) {
        #pragma unroll
        for (int ni = 0; ni < 8; ni++) {
            int gm = m0 + wm*32 + mi*16 + lr4;
            int gn = n0 + wn*64 + ni*8 + 2*lc4;
            float b0 = bias[gn], b1 = bias[gn+1];
            float v00 = acc[mi][ni][0] + b0, v01 = acc[mi][ni][1] + b1;
            float v10 = acc[mi][ni][2] + b0, v11 = acc[mi][ni][3] + b1;
            if (MODE == 2) {
                const float* r0 = res + (size_t)gm * N + gn;
                const float* r1 = res + (size_t)(gm+8) * N + gn;
                v00 += r0[0]; v01 += r0[1]; v10 += r1[0]; v11 += r1[1];
            }
            *(float2*)(C + (size_t)gm * N + gn)     = make_float2(v00, v01);
            *(float2*)(C + (size_t)(gm+8) * N + gn) = make_float2(v10, v11);
        }
    }
}

// ---------------------------------------------------------------------------
// Repack qkv [M,768] -> bf16 Q (roped + scaled by 0.125*log2e), K (roped), V.
// ---------------------------------------------------------------------------
__global__ __launch_bounds__(256) void repack_rope_kernel(const float* __restrict__ kp)
{
    int idx = blockIdx.x * blockDim.x + threadIdx.x;   // B*H*S*32 pairs
    int d2 = idx & 31;
    int s  = (idx >> 5) & (SL - 1);
    int h  = (idx >> 16) & (HN - 1);
    int b  = idx >> 18;

    int gm = b * SL + s;
    const float* src = g_qkv + (size_t)gm * 768 + h * 192 + 6 * d2;
    float q0 = src[0], k0 = src[1], v0 = src[2];
    float q1 = src[3], k1 = src[4], v1 = src[5];

    const int SIN_OFF = BD * SL * DH;
    int kb = (b * SL + s) * DH + (d2 << 1);
    float c0 = kp[kb],           c1 = kp[kb + 1];
    float s0 = kp[SIN_OFF + kb], s1 = kp[SIN_OFF + kb + 1];

    int base = (((b * HN + h) * SL) + s) * DH + (d2 << 1);
    const float scale = 0.125f * 1.4426950408889634f;   // Dh^-0.5 * log2(e)
    *(__nv_bfloat162*)&g_Qh[base] =
        __floats2bfloat162_rn((q0*c0 - q1*s0)*scale, (q1*c1 + q0*s1)*scale);
    *(__nv_bfloat162*)&g_Kh[base] =
        __floats2bfloat162_rn(k0*c0 - k1*s0, k1*c1 + k0*s1);
    *(__nv_bfloat162*)&g_Vr[base] = __floats2bfloat162_rn(v0, v1);
}

// ---------------------------------------------------------------------------
// V transpose: g_Vr [bh][s][d] -> g_Vt [bh][d][s], 64x64 smem tiles
// ---------------------------------------------------------------------------
__global__ __launch_bounds__(256) void vtrans_kernel()
{
    __shared__ uint32_t tile[64*33];
    const int t = threadIdx.x;
    const int bh = blockIdx.y;
    const int s0 = blockIdx.x << 6;

    {
        int sr = t >> 2, wc = (t & 3) * 8;
        const uint32_t* src = (const uint32_t*)(g_Vr + (size_t)bh*SL*DH + (size_t)(s0+sr)*DH) + wc;
        #pragma unroll
        for (int i = 0; i < 8; i++) tile[sr*33 + wc + i] = src[i];
    }
    __syncthreads();
    {
        int d = t >> 2, sc = (t & 3) * 16;
        uint32_t outw[8];
        #pragma unroll
        for (int j = 0; j < 8; j++) {
            uint32_t w0 = tile[(sc + 2*j    )*33 + (d >> 1)];
            uint32_t w1 = tile[(sc + 2*j + 1)*33 + (d >> 1)];
            uint32_t lo = (d & 1) ? (w0 >> 16) : (w0 & 0xffffu);
            uint32_t hi = (d & 1) ? (w1 >> 16) : (w1 & 0xffffu);
            outw[j] = lo | (hi << 16);
        }
        uint32_t* dst = (uint32_t*)(g_Vt + (size_t)bh*DH*SL + (size_t)d*SL + s0 + sc);
        *(uint4*)dst       = make_uint4(outw[0], outw[1], outw[2], outw[3]);
        *(uint4*)(dst + 4) = make_uint4(outw[4], outw[5], outw[6], outw[7]);
    }
}

// ---------------------------------------------------------------------------
// Flash attention, bf16 m16n8k16, register fragment-passing for P (no smem P),
// exp2 softmax, cp.async 2-stage K/V. CTA: 64 q x 64-key tiles, 8 warps 4Mx2N.
// Each warp: QK over its 32 keys -> P in registers -> PV (its keys, all 64 d,
// partial O). Epilogue: O and l reduced across the 2 N-warps.
// Writes ctx as bf16.
// ---------------------------------------------------------------------------
#define KW 36   // smem row stride in 4B words (72 bf16)
__global__ __launch_bounds__(256, 3) void attn_kernel(__nv_bfloat16* __restrict__ ctx)
{
    __shared__ uint32_t Ks[2][64*KW];
    __shared__ uint32_t Vts[2][64*KW];
    __shared__ float lsum[2][64];

    const int t = threadIdx.x;
    const int w = t >> 5, wm = w & 3, wn = w >> 2;
    const int lane = t & 31, g = lane >> 2, tg = lane & 3;
    const int r8 = lane & 7;
    const int selA = (lane >> 3) & 1;
    const int selB = (lane >> 4) & 1;
    const int bh = blockIdx.y;
    const int m0 = blockIdx.x << 6;

    const __nv_bfloat16* Qb  = g_Qh + (size_t)bh * SL * DH;
    const __nv_bfloat16* Kb  = g_Kh + (size_t)bh * SL * DH;
    const __nv_bfloat16* Vtb = g_Vt + (size_t)bh * DH * SL;

    // Q fragments in registers: 4 k-steps x 4 regs (bf16 pairs)
    uint32_t qf[4][4];
    {
        const uint32_t* Qw = (const uint32_t*)Qb;   // 32 words per row
        int r = m0 + wm*16 + g;
        #pragma unroll
        for (int kk = 0; kk < 4; kk++) {
            qf[kk][0] = Qw[(size_t)r    *32 + kk*8 + tg];
            qf[kk][1] = Qw[(size_t)(r+8)*32 + kk*8 + tg];
            qf[kk][2] = Qw[(size_t)r    *32 + kk*8 + tg + 4];
            qf[kk][3] = Qw[(size_t)(r+8)*32 + kk*8 + tg + 4];
        }
    }

    const int ldrow = t >> 2, lb = (t & 3) * 32;
    uint32_t sK = (uint32_t)__cvta_generic_to_shared(&Ks[0][0]);
    uint32_t sV = (uint32_t)__cvta_generic_to_shared(&Vts[0][0]);
    const uint32_t stage = 64*KW*4;

    auto issue_kv = [&](int n0, int buf) {
        const char* kg = (const char*)(Kb + (size_t)(n0 + ldrow) * DH) + lb;
        uint32_t dk = sK + buf*stage + ldrow*144 + lb;
        cp16(dk, kg); cp16(dk + 16, kg + 16);
        const char* vg = (const char*)(Vtb + (size_t)ldrow * SL + n0) + lb;
        uint32_t dv = sV + buf*stage + ldrow*144 + lb;
        cp16(dv, vg); cp16(dv + 16, vg + 16);
        cp_commit();
    };

    issue_kv(0, 0);

    float o[8][4] = {};       // partial O over this warp's keys, all 64 d
    float l0 = 0.f, l1 = 0.f;

    const int rowB = r8 + selB*8;
    const int colB = selA*4;

    for (int n0 = 0; n0 < SL; n0 += 64) {
        const int cur = (n0 >> 6) & 1;
        cp_wait<0>();
        __syncthreads();
        if (n0 + 64 < SL) issue_kv(n0 + 64, cur ^ 1);

        const uint32_t sKc = sK + cur*stage;
        const uint32_t sVc = sV + cur*stage;

        // S = Q K^T  (warp tile 16 q x 32 keys)
        float s[4][4] = {};
        #pragma unroll
        for (int kk = 0; kk < 4; kk++) {
            #pragma unroll
            for (int nip = 0; nip < 4; nip += 2) {
                uint32_t b0a, b1a, b0b, b1b;
                ldsm4(b0a, b1a, b0b, b1b,
                      sKc + (uint32_t)(((wn*32 + nip*8 + rowB)*KW + kk*8 + colB) * 4));
                mma16(s[nip],   qf[kk], b0a, b1a);
                mma16(s[nip+1], qf[kk], b0b, b1b);
            }
        }

        // P = exp2(S), partial row sums
        float rs0 = 0.f, rs1 = 0.f;
        #pragma unroll
        for (int ni = 0; ni < 4; ni++) {
            s[ni][0] = exp2f(s[ni][0]); s[ni][1] = exp2f(s[ni][1]);
            s[ni][2] = exp2f(s[ni][2]); s[ni][3] = exp2f(s[ni][3]);
            rs0 += s[ni][0] + s[ni][1];
            rs1 += s[ni][2] + s[ni][3];
        }
        rs0 += __shfl_xor_sync(0xffffffffu, rs0, 1);
        rs0 += __shfl_xor_sync(0xffffffffu, rs0, 2);
        rs1 += __shfl_xor_sync(0xffffffffu, rs1, 1);
        rs1 += __shfl_xor_sync(0xffffffffu, rs1, 2);
        l0 += rs0; l1 += rs1;

        // pack P into mma A-fragments (registers only; C-frag layout == A-frag layout)
        uint32_t pf[2][4];
        #pragma unroll
        for (int ks = 0; ks < 2; ks++) {
            pf[ks][0] = packbf(s[2*ks][0],   s[2*ks][1]);
            pf[ks][1] = packbf(s[2*ks][2],   s[2*ks][3]);
            pf[ks][2] = packbf(s[2*ks+1][0], s[2*ks+1][1]);
            pf[ks][3] = packbf(s[2*ks+1][2], s[2*ks+1][3]);
        }

        // O += P V  over this warp's 32 keys (2 k-steps of 16), all 64 d
        #pragma unroll
        for (int ks = 0; ks < 2; ks++) {
            #pragma unroll
            for (int nip = 0; nip < 8; nip += 2) {
                uint32_t b0a, b1a, b0b, b1b;
                ldsm4(b0a, b1a, b0b, b1b,
                      sVc + (uint32_t)(((nip*8 + rowB)*KW + wn*16 + ks*8 + colB) * 4));
                mma16(o[nip],   pf[ks], b0a, b1a);
                mma16(o[nip+1], pf[ks], b0b, b1b);
            }
        }
    }

    // l partial sums to smem
    if (tg == 0) {
        int pr = wm*16 + g;
        lsum[wn][pr] = l0; lsum[wn][pr + 8] = l1;
    }

    // O reduction across the 2 N-warps: wn=1 writes partial O into smem
    // (reusing Ks as a float buffer; all K reads are done), wn=0 adds.
    float* Osm = (float*)&Ks[0][0];   // stride 68 floats per row, 64 rows
    __syncthreads();                  // everyone done reading Ks/lsum writes visible
    if (wn == 1) {
        int row = wm*16 + g;
        #pragma unroll
        for (int ni = 0; ni < 8; ni++) {
            int col = ni*8 + 2*tg;
            *(float2*)&Osm[row*68 + col]     = make_float2(o[ni][0], o[ni][1]);
            *(float2*)&Osm[(row+8)*68 + col] = make_float2(o[ni][2], o[ni][3]);
        }
    }
    __syncthreads();
    if (wn == 0) {
        int pr = wm*16 + g;
        float inv0 = 1.0f / (lsum[0][pr]     + lsum[1][pr]);
        float inv1 = 1.0f / (lsum[0][pr + 8] + lsum[1][pr + 8]);
        const int b = bh >> 2, h = bh & 3;
        size_t r0 = (size_t)(b * SL + m0 + pr) * DM + h * DH;
        size_t r1 = r0 + 8 * DM;
        #pragma unroll
        for (int ni = 0; ni < 8; ni++) {
            int col = ni*8 + 2*tg;
            float2 p0 = *(float2*)&Osm[pr*68 + col];
            float2 p1 = *(float2*)&Osm[(pr+8)*68 + col];
            *(uint32_t*)(ctx + r0 + col) = packbf((o[ni][0]+p0.x)*inv0, (o[ni][1]+p0.y)*inv0);
            *(uint32_t*)(ctx + r1 + col) = packbf((o[ni][2]+p1.x)*inv1, (o[ni][3]+p1.y)*inv1);
        }
    }
}

// ---------------------------------------------------------------------------
// LayerNorm (biased var) + exact GELU, in place on g_ff rows of 512
// ---------------------------------------------------------------------------
__global__ __launch_bounds__(256) void ln_gelu_kernel(const float* __restrict__ g,
                                                      const float* __restrict__ bb)
{
    int row = blockIdx.x;
    float* xr = g_ff + (size_t)row * 512;
    int t = threadIdx.x;
    float v0 = xr[t], v1 = xr[t + 256];
    float sum = v0 + v1;
    float sq  = v0 * v0 + v1 * v1;
    #pragma unroll
    for (int off = 16; off > 0; off >>= 1) {
        sum += __shfl_xor_sync(0xffffffffu, sum, off);
        sq  += __shfl_xor_sync(0xffffffffu, sq,  off);
    }
    __shared__ float ssum[8], ssq[8];
    __shared__ float smean, srstd;
    int w = t >> 5;
    if ((t & 31) == 0) { ssum[w] = sum; ssq[w] = sq; }
    __syncthreads();
    if (t == 0) {
        float S = 0.f, Q = 0.f;
        #pragma unroll
        for (int i = 0; i < 8; i++) { S += ssum[i]; Q += ssq[i]; }
        float mean = S * (1.0f / 512.0f);
        float var  = Q * (1.0f / 512.0f) - mean * mean;
        smean = mean;
        srstd = rsqrtf(var + 1e-5f);
    }
    __syncthreads();
    float mean = smean, rstd = srstd;

    float y0 = (v0 - mean) * rstd * g[t] + bb[t];
    float y1 = (v1 - mean) * rstd * g[t + 256] + bb[t + 256];
    xr[t]       = 0.5f * y0 * (1.0f + erff(y0 * 0.70710678118654752f));
    xr[t + 256] = 0.5f * y1 * (1.0f + erff(y1 * 0.70710678118654752f));
}

// ---------------------------------------------------------------------------
extern "C" void kernel_launch(void* const* d_in, const int* in_sizes, int n_in,
                              void* d_out, int out_size)
{
    (void)in_sizes; (void)n_in; (void)out_size;
    const float* desc   = (const float*)d_in[0];
    const float* kp     = (const float*)d_in[1];
    const float* Wqkv_w = (const float*)d_in[2];
    const float* Wqkv_b = (const float*)d_in[3];
    const float* Wo_w   = (const float*)d_in[4];
    const float* Wo_b   = (const float*)d_in[5];
    const float* W1_w   = (const float*)d_in[6];
    const float* W1_b   = (const float*)d_in[7];
    const float* ln_g   = (const float*)d_in[8];
    const float* ln_b   = (const float*)d_in[9];
    const float* W2_w   = (const float*)d_in[10];
    const float* W2_b   = (const float*)d_in[11];
    float* out = (float*)d_out;

    float *pqkv = nullptr, *pmsg = nullptr, *pff = nullptr;
    __nv_bfloat16 *pdesch = nullptr, *pWh = nullptr, *pWoh = nullptr, *pctxh = nullptr;
    cudaGetSymbolAddress((void**)&pqkv, g_qkv);
    cudaGetSymbolAddress((void**)&pmsg, g_msg);
    cudaGetSymbolAddress((void**)&pff,  g_ff);
    cudaGetSymbolAddress((void**)&pdesch, g_desch);
    cudaGetSymbolAddress((void**)&pWh,    g_Wqkvh);
    cudaGetSymbolAddress((void**)&pWoh,   g_Woh);
    cudaGetSymbolAddress((void**)&pctxh,  g_ctxh);

    cudaFuncSetAttribute(gemm_tc<0, false>, cudaFuncAttributeMaxDynamicSharedMemorySize, GEMM_SMEM);
    cudaFuncSetAttribute(gemm_tc<0, true>,  cudaFuncAttributeMaxDynamicSharedMemorySize, GEMM_SMEM);
    cudaFuncSetAttribute(gemm_tc<2, false>, cudaFuncAttributeMaxDynamicSharedMemorySize, GEMM_SMEM);
    cudaFuncSetAttribute(gemm_bf16,         cudaFuncAttributeMaxDynamicSharedMemorySize, GEMMH_SMEM);

    // 0. bf16 copies of desc, Wqkv_w, Wo_w
    f2bf_kernel<<<(MR * DM) / 1024, 256>>>(desc, pdesch);
    f2bf_kernel<<<(768 * DM) / 1024, 256>>>(Wqkv_w, pWh);
    f2bf_kernel<<<(DM * DM) / 1024, 256>>>(Wo_w, pWoh);

    // 1. QKV projection (bf16 tensor cores)
    gemm_bf16<<<dim3(768 / 128, MR / 128), 256, GEMMH_SMEM>>>(
        pdesch, pWh, Wqkv_b, pqkv, MR, 768, 256);

    // 2. Repack to bf16 [B,H,S,Dh] + RoPE (+scale on Q)
    repack_rope_kernel<<<(BD * HN * SL * 32) / 256, 256>>>(kp);

    // 2b. V transpose -> [B,H,Dh,S]
    vtrans_kernel<<<dim3(SL / 64, BD * HN), 256>>>();

    // 3. Attention -> ctx bf16 [B,S,D]
    attn_kernel<<<dim3(SL / 64, BD * HN), 256>>>(pctxh);

    // 4. message = ctx @ Wo^T + b  (bf16 tensor cores)
    gemm_bf16<<<dim3(DM / 128, MR / 128), 256, GEMMH_SMEM>>>(
        pctxh, pWoh, Wo_b, pmsg, MR, DM, DM);

    // 5. ff = concat(desc, msg) @ W1^T + b
    gemm_tc<0, true><<<dim3(512 / 128, MR / 128), 256, GEMM_SMEM>>>(
        desc, pmsg, W1_w, W1_b, pff, nullptr, MR, 512, 512);

    // 6. LayerNorm + GELU in place
    ln_gelu_kernel<<<MR, 256>>>(ln_g, ln_b);

    // 7. out = desc + ff @ W2^T + b
    gemm_tc<2, false><<<dim3(DM / 128, MR / 128), 256, GEMM_SMEM>>>(
        pff, nullptr, W2_w, W2_b, out, desc, MR, DM, 512);
}